// round 7
// baseline (speedup 1.0000x reference)
#include <cuda_runtime.h>
#include <cuda_bf16.h>
#include <math.h>
#include <stdint.h>

// Problem dims
constexpr int Bn = 2, Sn = 2048, Hn = 4096, NHn = 32, NKVn = 8, HDn = 128;
constexpr int Mn = Bn * Sn;
constexpr float QK_SCALE = 0.08838834764831845f; // 1/sqrt(128)
constexpr float L2E = 1.4426950408889634f;

// bf16 split scratch
__device__ __nv_bfloat16 g_Xhi[(size_t)Mn * Hn];   // X split; reused for attn out
__device__ __nv_bfloat16 g_Xlo[(size_t)Mn * Hn];
__device__ __nv_bfloat16 g_WqThi[(size_t)4096 * 4096];
__device__ __nv_bfloat16 g_WqTlo[(size_t)4096 * 4096];
__device__ __nv_bfloat16 g_WkThi[(size_t)1024 * 4096];
__device__ __nv_bfloat16 g_WkTlo[(size_t)1024 * 4096];
__device__ __nv_bfloat16 g_WvThi[(size_t)1024 * 4096];
__device__ __nv_bfloat16 g_WvTlo[(size_t)1024 * 4096];
__device__ __nv_bfloat16 g_WoThi[(size_t)4096 * 4096];
__device__ __nv_bfloat16 g_WoTlo[(size_t)4096 * 4096];
// attention operands (hi/lo, post-RoPE), written by GEMM epilogues
__device__ __nv_bfloat16 g_Qh[(size_t)Bn * NHn * Sn * HDn];
__device__ __nv_bfloat16 g_Ql[(size_t)Bn * NHn * Sn * HDn];
__device__ __nv_bfloat16 g_Kh[(size_t)Bn * NKVn * Sn * HDn];
__device__ __nv_bfloat16 g_Kl[(size_t)Bn * NKVn * Sn * HDn];
__device__ __nv_bfloat16 g_Vh[(size_t)Bn * NKVn * Sn * HDn];
__device__ __nv_bfloat16 g_Vl[(size_t)Bn * NKVn * Sn * HDn];
// RoPE cos/sin table [s][d<64]
__device__ float2 g_RT[(size_t)Sn * 64];

// ---------------------------------------------------------------------------
// helpers
// ---------------------------------------------------------------------------
__device__ __forceinline__ uint32_t smem_u32(const void* p) {
    uint32_t a;
    asm("{ .reg .u64 t; cvta.to.shared.u64 t, %1; cvt.u32.u64 %0, t; }"
        : "=r"(a) : "l"(p));
    return a;
}
__device__ __forceinline__ void cpa16(uint32_t dst, const void* src) {
    asm volatile("cp.async.cg.shared.global [%0], [%1], 16;"
                 :: "r"(dst), "l"(src) : "memory");
}
__device__ __forceinline__ void ldsm4(uint32_t& r0, uint32_t& r1,
                                      uint32_t& r2, uint32_t& r3, uint32_t a) {
    asm volatile("ldmatrix.sync.aligned.m8n8.x4.shared.b16 {%0,%1,%2,%3}, [%4];"
                 : "=r"(r0), "=r"(r1), "=r"(r2), "=r"(r3) : "r"(a));
}
__device__ __forceinline__ void ldsm4t(uint32_t& r0, uint32_t& r1,
                                       uint32_t& r2, uint32_t& r3, uint32_t a) {
    asm volatile("ldmatrix.sync.aligned.m8n8.x4.trans.shared.b16 {%0,%1,%2,%3}, [%4];"
                 : "=r"(r0), "=r"(r1), "=r"(r2), "=r"(r3) : "r"(a));
}
__device__ __forceinline__ void mma_bf16(float* c, const uint32_t* a,
                                         const uint32_t* b) {
    asm volatile(
        "mma.sync.aligned.m16n8k16.row.col.f32.bf16.bf16.f32 "
        "{%0,%1,%2,%3}, {%4,%5,%6,%7}, {%8,%9}, {%0,%1,%2,%3};"
        : "+f"(c[0]), "+f"(c[1]), "+f"(c[2]), "+f"(c[3])
        : "r"(a[0]), "r"(a[1]), "r"(a[2]), "r"(a[3]), "r"(b[0]), "r"(b[1]));
}
// fast exp2 on the FMA pipe (y <= 0; clamp makes masked rows vanish)
__device__ __forceinline__ float fexp2(float y) {
    y = fmaxf(y, -126.f);
    float fl = floorf(y);
    float f = y - fl;
    float p = 1.8775767e-3f;
    p = fmaf(p, f, 8.9893397e-3f);
    p = fmaf(p, f, 5.5826318e-2f);
    p = fmaf(p, f, 2.4015361e-1f);
    p = fmaf(p, f, 6.9315308e-1f);
    p = fmaf(p, f, 9.9999994e-1f);
    return __int_as_float(((int)fl + 127) << 23) * p;
}
__device__ __forceinline__ uint32_t pack_bf2(float a, float b) {
    __nv_bfloat162 v = __floats2bfloat162_rn(a, b);
    return *reinterpret_cast<uint32_t*>(&v);
}
__device__ __forceinline__ uint32_t pack_bf2_res(float a, float b, uint32_t hi) {
    __nv_bfloat162 hv = *reinterpret_cast<__nv_bfloat162*>(&hi);
    return pack_bf2(a - __bfloat162float(hv.x), b - __bfloat162float(hv.y));
}

// ---------------------------------------------------------------------------
// RoPE table (accurate powf + sincosf, computed once; pos == s)
// ---------------------------------------------------------------------------
__global__ void ropetab_kernel()
{
    int idx = blockIdx.x * 256 + threadIdx.x;   // Sn*64 = 131072
    int s = idx >> 6, d = idx & 63;
    float inv = powf(10000.f, -(float)d / 64.f);
    float sn, cs;
    sincosf((float)s * inv, &sn, &cs);
    g_RT[idx] = make_float2(cs, sn);
}

// ---------------------------------------------------------------------------
// Split conversion: x -> (hi, lo) bf16
// ---------------------------------------------------------------------------
__global__ void split_kernel(const float* __restrict__ x,
                             __nv_bfloat16* __restrict__ hi,
                             __nv_bfloat16* __restrict__ lo, int n4)
{
    int i = blockIdx.x * 256 + threadIdx.x;
    if (i >= n4) return;
    float4 v = reinterpret_cast<const float4*>(x)[i];
    __nv_bfloat16 h0 = __float2bfloat16(v.x), h1 = __float2bfloat16(v.y);
    __nv_bfloat16 h2 = __float2bfloat16(v.z), h3 = __float2bfloat16(v.w);
    __nv_bfloat16 l0 = __float2bfloat16(v.x - __bfloat162float(h0));
    __nv_bfloat16 l1 = __float2bfloat16(v.y - __bfloat162float(h1));
    __nv_bfloat16 l2 = __float2bfloat16(v.z - __bfloat162float(h2));
    __nv_bfloat16 l3 = __float2bfloat16(v.w - __bfloat162float(h3));
    reinterpret_cast<__nv_bfloat162*>(hi)[i * 2 + 0] = __halves2bfloat162(h0, h1);
    reinterpret_cast<__nv_bfloat162*>(hi)[i * 2 + 1] = __halves2bfloat162(h2, h3);
    reinterpret_cast<__nv_bfloat162*>(lo)[i * 2 + 0] = __halves2bfloat162(l0, l1);
    reinterpret_cast<__nv_bfloat162*>(lo)[i * 2 + 1] = __halves2bfloat162(l2, l3);
}

// ---------------------------------------------------------------------------
// Transpose + split: W[K][N] fp32 -> T{hi,lo}[N][K] bf16
// ---------------------------------------------------------------------------
__global__ void tsplit_kernel(const float* __restrict__ W,
                              __nv_bfloat16* __restrict__ Thi,
                              __nv_bfloat16* __restrict__ Tlo, int K, int N)
{
    __shared__ float t[32][33];
    int tx = threadIdx.x, ty = threadIdx.y;
    int bx = blockIdx.x, by = blockIdx.y;
#pragma unroll
    for (int i = 0; i < 4; i++) {
        int r = by * 32 + ty + i * 8;
        t[ty + i * 8][tx] = W[(size_t)r * N + bx * 32 + tx];
    }
    __syncthreads();
#pragma unroll
    for (int i = 0; i < 4; i++) {
        int n = bx * 32 + ty + i * 8;
        int k = by * 32 + tx;
        float v = t[tx][ty + i * 8];
        __nv_bfloat16 h = __float2bfloat16(v);
        __nv_bfloat16 l = __float2bfloat16(v - __bfloat162float(h));
        Thi[(size_t)n * K + k] = h;
        Tlo[(size_t)n * K + k] = l;
    }
}

// ---------------------------------------------------------------------------
// bf16 split GEMM on mma.sync (round-4 mainloop, fused epilogues):
// MODE 0: fp32 C row-major (output projection -> d_out)
// MODE 1: RoPE + split -> Oh/Ol in Q layout [b][h][s][d], scale=QK_SCALE
// MODE 2: RoPE + split -> Oh/Ol in KV layout, scale=1
// MODE 3: split only   -> Oh/Ol in KV layout (V)
// ---------------------------------------------------------------------------
constexpr int TROW = 144;
constexpr int TTILE = 128 * TROW;
constexpr int TSTAGE = 4 * TTILE;
constexpr int HG_SMEM = 2 * TSTAGE;      // 147456 B (>= 128*132*4 staging)

template <int MODE>
__global__ __launch_bounds__(256) void hgemm_kernel(
    const __nv_bfloat16* __restrict__ Ahi, const __nv_bfloat16* __restrict__ Alo,
    const __nv_bfloat16* __restrict__ Bhi, const __nv_bfloat16* __restrict__ Blo,
    float* __restrict__ C,
    __nv_bfloat16* __restrict__ Oh, __nv_bfloat16* __restrict__ Ol,
    int N, int K)
{
    extern __shared__ char smem[];
    const uint32_t sb = smem_u32(smem);

    const int tid = threadIdx.x;
    const int wid = tid >> 5, lane = tid & 31;
    const int g = lane >> 2, t4 = lane & 3;
    const int wr = wid >> 2, wc = wid & 3;
    const int wm = wr * 64, wn = wc * 32;
    const int m0 = blockIdx.y * 128, n0 = blockIdx.x * 128;

    const __nv_bfloat16* Ah = Ahi + (size_t)m0 * K;
    const __nv_bfloat16* Al = Alo + (size_t)m0 * K;
    const __nv_bfloat16* Bh = Bhi + (size_t)n0 * K;
    const __nv_bfloat16* Bl = Blo + (size_t)n0 * K;

    float c[4][4][4];
#pragma unroll
    for (int mi = 0; mi < 4; mi++)
#pragma unroll
        for (int ni = 0; ni < 4; ni++)
#pragma unroll
            for (int r = 0; r < 4; r++) c[mi][ni][r] = 0.f;

    const int rb = tid >> 3;
    const int c8 = tid & 7;

    auto load_chunk = [&](int stage, int koff) {
        const uint32_t base = sb + stage * TSTAGE;
#pragma unroll
        for (int i = 0; i < 16; i++) {
            const int tile = i >> 2;
            const int r = (i & 3) * 32 + rb;
            const __nv_bfloat16* s =
                (tile == 0) ? Ah : (tile == 1) ? Al : (tile == 2) ? Bh : Bl;
            cpa16(base + tile * TTILE + r * TROW + c8 * 16,
                  s + (size_t)r * K + koff + c8 * 8);
        }
        asm volatile("cp.async.commit_group;" ::: "memory");
    };

    const int NC = K / 64;
    load_chunk(0, 0);
    if (NC > 1) load_chunk(1, 64);

    const int arow_off = (lane & 7) + ((lane >> 3) & 1) * 8;
    const int acol_off = (lane >> 4) * 8;
    const int brow_off = (lane & 7) + (lane >> 4) * 8;
    const int bcol_off = ((lane >> 3) & 1) * 8;

    for (int ch = 0; ch < NC; ch++) {
        if (ch + 1 < NC)
            asm volatile("cp.async.wait_group 1;" ::: "memory");
        else
            asm volatile("cp.async.wait_group 0;" ::: "memory");
        __syncthreads();

        const uint32_t st = sb + (ch & 1) * TSTAGE;
        const uint32_t ah_b = st, al_b = st + TTILE;
        const uint32_t bh_b = st + 2 * TTILE, bl_b = st + 3 * TTILE;

#pragma unroll
        for (int kk = 0; kk < 64; kk += 16) {
            uint32_t fah[4][4], fal[4][4], fbh[4][2], fbl[4][2];
#pragma unroll
            for (int mi = 0; mi < 4; mi++) {
                const uint32_t ro = (wm + mi * 16 + arow_off) * TROW +
                                    (kk + acol_off) * 2;
                ldsm4(fah[mi][0], fah[mi][1], fah[mi][2], fah[mi][3], ah_b + ro);
                ldsm4(fal[mi][0], fal[mi][1], fal[mi][2], fal[mi][3], al_b + ro);
            }
#pragma unroll
            for (int bt = 0; bt < 2; bt++) {
                const uint32_t ro = (wn + bt * 16 + brow_off) * TROW +
                                    (kk + bcol_off) * 2;
                ldsm4(fbh[2 * bt][0], fbh[2 * bt][1],
                      fbh[2 * bt + 1][0], fbh[2 * bt + 1][1], bh_b + ro);
                ldsm4(fbl[2 * bt][0], fbl[2 * bt][1],
                      fbl[2 * bt + 1][0], fbl[2 * bt + 1][1], bl_b + ro);
            }
#pragma unroll
            for (int mi = 0; mi < 4; mi++)
#pragma unroll
                for (int ni = 0; ni < 4; ni++) {
                    mma_bf16(c[mi][ni], fah[mi], fbh[ni]);
                    mma_bf16(c[mi][ni], fah[mi], fbl[ni]);
                    mma_bf16(c[mi][ni], fal[mi], fbh[ni]);
                }
        }
        __syncthreads();
        if (ch + 2 < NC) load_chunk(ch & 1, (ch + 2) * 64);
    }

    if (MODE == 0) {
        // fp32 row-major store (output projection)
#pragma unroll
        for (int mi = 0; mi < 4; mi++)
#pragma unroll
            for (int ni = 0; ni < 4; ni++) {
                const int row0 = m0 + wm + mi * 16 + g;
                const int col = n0 + wn + ni * 8 + 2 * t4;
#pragma unroll
                for (int half = 0; half < 2; half++) {
                    const int m = row0 + half * 8;
                    float2 v = half ? make_float2(c[mi][ni][2], c[mi][ni][3])
                                    : make_float2(c[mi][ni][0], c[mi][ni][1]);
                    *reinterpret_cast<float2*>(&C[(size_t)m * N + col]) = v;
                }
            }
    } else if (MODE == 3) {
        // split-only, KV layout (V projection)
        const int hh = n0 >> 7;
#pragma unroll
        for (int mi = 0; mi < 4; mi++)
#pragma unroll
            for (int ni = 0; ni < 4; ni++) {
                const int row0 = m0 + wm + mi * 16 + g;
                const int col = wn + ni * 8 + 2 * t4;
#pragma unroll
                for (int half = 0; half < 2; half++) {
                    const int m = row0 + half * 8;
                    float v0 = half ? c[mi][ni][2] : c[mi][ni][0];
                    float v1 = half ? c[mi][ni][3] : c[mi][ni][1];
                    const int bb = m >> 11, s = m & 2047;
                    size_t base =
                        (((size_t)(bb * NKVn + hh) * Sn) + s) * HDn + col;
                    uint32_t hv = pack_bf2(v0, v1);
                    *reinterpret_cast<uint32_t*>(&Oh[base]) = hv;
                    *reinterpret_cast<uint32_t*>(&Ol[base]) =
                        pack_bf2_res(v0, v1, hv);
                }
            }
    } else {
        // MODE 1/2: stage tile to smem, apply RoPE pairing (d, d+64), split.
        float* stg = reinterpret_cast<float*>(smem);
#pragma unroll
        for (int mi = 0; mi < 4; mi++)
#pragma unroll
            for (int ni = 0; ni < 4; ni++) {
                const int rl = wm + mi * 16 + g;
                const int cl = wn + ni * 8 + 2 * t4;
                stg[rl * 132 + cl] = c[mi][ni][0];
                stg[rl * 132 + cl + 1] = c[mi][ni][1];
                stg[(rl + 8) * 132 + cl] = c[mi][ni][2];
                stg[(rl + 8) * 132 + cl + 1] = c[mi][ni][3];
            }
        __syncthreads();
        const int heads = (MODE == 1) ? NHn : NKVn;
        const float scale = (MODE == 1) ? QK_SCALE : 1.f;
        const int hh = n0 >> 7;
#pragma unroll
        for (int i = 0; i < 32; i++) {
            int p = tid + i * 256;          // 8192 pairs
            int r = p >> 6, d = p & 63;
            int m = m0 + r;
            int bb = m >> 11, s = m & 2047;
            float x0 = stg[r * 132 + d];
            float x1 = stg[r * 132 + d + 64];
            float2 t = g_RT[s * 64 + d];
            float r0 = (x0 * t.x - x1 * t.y) * scale;
            float r1 = (x1 * t.x + x0 * t.y) * scale;
            __nv_bfloat16 h0 = __float2bfloat16(r0);
            __nv_bfloat16 h1 = __float2bfloat16(r1);
            size_t base = (((size_t)(bb * heads + hh) * Sn) + s) * HDn;
            Oh[base + d] = h0;
            Oh[base + d + 64] = h1;
            Ol[base + d] = __float2bfloat16(r0 - __bfloat162float(h0));
            Ol[base + d + 64] = __float2bfloat16(r1 - __bfloat162float(h1));
        }
    }
}

// ---------------------------------------------------------------------------
// Flash attention on mma.sync, bf16 split, BQ=128, BK=64, 8 warps.
// Writes hi/lo bf16 output straight into g_Xhi/g_Xlo (O-GEMM A operand).
// ---------------------------------------------------------------------------
constexpr int ARB = 272;                  // padded row bytes (136 bf16)
constexpr int KVT = 64 * ARB;             // one 64x128 bf16 tile = 17408 B
constexpr int ASTG = 4 * KVT;             // Kh,Kl,Vh,Vl per stage = 69632 B
constexpr int AT_SMEM = 2 * ASTG;         // 139264 B

__global__ __launch_bounds__(256, 1) void attn_mma_kernel()
{
    extern __shared__ char smem[];
    const uint32_t sb = smem_u32(smem);
    const int qt = blockIdx.x, h = blockIdx.y, b = blockIdx.z;
    const int tid = threadIdx.x, wid = tid >> 5, lane = tid & 31;
    const int g = lane >> 2, t4 = lane & 3;
    const int wm = wid * 16;
    const int kvh = h >> 2;
    const int NT = 2 * (qt + 1);

    const __nv_bfloat16* Qhp = g_Qh + ((size_t)(b * NHn + h) * Sn + qt * 128) * HDn;
    const __nv_bfloat16* Qlp = g_Ql + ((size_t)(b * NHn + h) * Sn + qt * 128) * HDn;
    const __nv_bfloat16* Khp = g_Kh + ((size_t)(b * NKVn + kvh) * Sn) * HDn;
    const __nv_bfloat16* Klp = g_Kl + ((size_t)(b * NKVn + kvh) * Sn) * HDn;
    const __nv_bfloat16* Vhp = g_Vh + ((size_t)(b * NKVn + kvh) * Sn) * HDn;
    const __nv_bfloat16* Vlp = g_Vl + ((size_t)(b * NKVn + kvh) * Sn) * HDn;

    // Q tiles -> stage1 region (reused for K/V after frags extracted)
    const uint32_t qhb = sb + ASTG, qlb = sb + ASTG + 34816;
#pragma unroll
    for (int i = 0; i < 8; i++) {
        int id = tid + i * 256, r = id >> 4, c = id & 15;
        cpa16(qhb + r * ARB + c * 16, Qhp + r * HDn + c * 8);
        cpa16(qlb + r * ARB + c * 16, Qlp + r * HDn + c * 8);
    }
    asm volatile("cp.async.commit_group;" ::: "memory");

    auto load_stage = [&](int stg, int t) {
        const uint32_t st = sb + stg * ASTG;
        const __nv_bfloat16* kh = Khp + (size_t)t * 64 * HDn;
        const __nv_bfloat16* kl = Klp + (size_t)t * 64 * HDn;
        const __nv_bfloat16* vh = Vhp + (size_t)t * 64 * HDn;
        const __nv_bfloat16* vl = Vlp + (size_t)t * 64 * HDn;
#pragma unroll
        for (int i = 0; i < 4; i++) {
            int id = tid + i * 256, r = id >> 4, c = id & 15;
            cpa16(st + 0 * KVT + r * ARB + c * 16, kh + r * HDn + c * 8);
            cpa16(st + 1 * KVT + r * ARB + c * 16, kl + r * HDn + c * 8);
            cpa16(st + 2 * KVT + r * ARB + c * 16, vh + r * HDn + c * 8);
            cpa16(st + 3 * KVT + r * ARB + c * 16, vl + r * HDn + c * 8);
        }
        asm volatile("cp.async.commit_group;" ::: "memory");
    };
    load_stage(0, 0);

    asm volatile("cp.async.wait_group 1;" ::: "memory");  // Q arrived
    __syncthreads();

    const int arow = (lane & 7) + ((lane >> 3) & 1) * 8;
    const int acolB = (lane >> 4) * 16;
    uint32_t qhf[8][4], qlf[8][4];
#pragma unroll
    for (int ks = 0; ks < 8; ks++) {
        uint32_t ro = (wm + arow) * ARB + ks * 32 + acolB;
        ldsm4(qhf[ks][0], qhf[ks][1], qhf[ks][2], qhf[ks][3], qhb + ro);
        ldsm4(qlf[ks][0], qlf[ks][1], qlf[ks][2], qlf[ks][3], qlb + ro);
    }
    __syncthreads();
    load_stage(1, 1);

    float o[16][4];
#pragma unroll
    for (int j = 0; j < 16; j++)
#pragma unroll
        for (int e = 0; e < 4; e++) o[j][e] = 0.f;
    float m0 = -1e30f, m1 = -1e30f, l0 = 0.f, l1 = 0.f;

    const int brow = (lane & 7) + (lane >> 4) * 8;
    const int bcolB = ((lane >> 3) & 1) * 16;
    const int vcolB = (lane >> 4) * 16;
    const int row0g = qt * 128 + wm + g;

    for (int t = 0; t < NT; t++) {
        if (t + 1 < NT)
            asm volatile("cp.async.wait_group 1;" ::: "memory");
        else
            asm volatile("cp.async.wait_group 0;" ::: "memory");
        __syncthreads();
        const uint32_t st = sb + (t & 1) * ASTG;

        // ---- scores S = Q K^T (3-pass split) ----
        float s[8][4];
#pragma unroll
        for (int j = 0; j < 8; j++)
#pragma unroll
            for (int e = 0; e < 4; e++) s[j][e] = 0.f;

#pragma unroll
        for (int ks = 0; ks < 8; ks++) {
#pragma unroll
            for (int gr = 0; gr < 4; gr++) {
                uint32_t kh4[4], kl4[4];
                uint32_t ro = st + (gr * 16 + brow) * ARB + ks * 32 + bcolB;
                ldsm4(kh4[0], kh4[1], kh4[2], kh4[3], ro);
                ldsm4(kl4[0], kl4[1], kl4[2], kl4[3], ro + KVT);
                mma_bf16(s[2 * gr], qhf[ks], kh4);
                mma_bf16(s[2 * gr], qhf[ks], kl4);
                mma_bf16(s[2 * gr], qlf[ks], kh4);
                mma_bf16(s[2 * gr + 1], qhf[ks], kh4 + 2);
                mma_bf16(s[2 * gr + 1], qhf[ks], kl4 + 2);
                mma_bf16(s[2 * gr + 1], qlf[ks], kh4 + 2);
            }
        }

        // ---- causal mask ----
        if (t >= 2 * qt) {
#pragma unroll
            for (int j = 0; j < 8; j++) {
                int c0 = t * 64 + j * 8 + 2 * t4;
                if (c0 > row0g)     s[j][0] = -1e30f;
                if (c0 + 1 > row0g) s[j][1] = -1e30f;
                if (c0 > row0g + 8)     s[j][2] = -1e30f;
                if (c0 + 1 > row0g + 8) s[j][3] = -1e30f;
            }
        }

        // ---- online softmax ----
        float tm0 = -1e30f, tm1 = -1e30f;
#pragma unroll
        for (int j = 0; j < 8; j++) {
            tm0 = fmaxf(tm0, fmaxf(s[j][0], s[j][1]));
            tm1 = fmaxf(tm1, fmaxf(s[j][2], s[j][3]));
        }
        tm0 = fmaxf(tm0, __shfl_xor_sync(0xffffffffu, tm0, 1));
        tm0 = fmaxf(tm0, __shfl_xor_sync(0xffffffffu, tm0, 2));
        tm1 = fmaxf(tm1, __shfl_xor_sync(0xffffffffu, tm1, 1));
        tm1 = fmaxf(tm1, __shfl_xor_sync(0xffffffffu, tm1, 2));
        float mn0 = fmaxf(m0, tm0), mn1 = fmaxf(m1, tm1);
        float cor0 = fexp2((m0 - mn0) * L2E);
        float cor1 = fexp2((m1 - mn1) * L2E);
        m0 = mn0; m1 = mn1;
#pragma unroll
        for (int j = 0; j < 16; j++) {
            o[j][0] *= cor0; o[j][1] *= cor0;
            o[j][2] *= cor1; o[j][3] *= cor1;
        }
        float rs0 = 0.f, rs1 = 0.f;
#pragma unroll
        for (int j = 0; j < 8; j++) {
            s[j][0] = fexp2((s[j][0] - mn0) * L2E);
            s[j][1] = fexp2((s[j][1] - mn0) * L2E);
            s[j][2] = fexp2((s[j][2] - mn1) * L2E);
            s[j][3] = fexp2((s[j][3] - mn1) * L2E);
            rs0 += s[j][0] + s[j][1];
            rs1 += s[j][2] + s[j][3];
        }
        rs0 += __shfl_xor_sync(0xffffffffu, rs0, 1);
        rs0 += __shfl_xor_sync(0xffffffffu, rs0, 2);
        rs1 += __shfl_xor_sync(0xffffffffu, rs1, 1);
        rs1 += __shfl_xor_sync(0xffffffffu, rs1, 2);
        l0 = l0 * cor0 + rs0;
        l1 = l1 * cor1 + rs1;

        // ---- O += P V ----
#pragma unroll
        for (int ks = 0; ks < 4; ks++) {
            uint32_t pha[4], pla[4];
            pha[0] = pack_bf2(s[2 * ks][0], s[2 * ks][1]);
            pha[1] = pack_bf2(s[2 * ks][2], s[2 * ks][3]);
            pha[2] = pack_bf2(s[2 * ks + 1][0], s[2 * ks + 1][1]);
            pha[3] = pack_bf2(s[2 * ks + 1][2], s[2 * ks + 1][3]);
            pla[0] = pack_bf2_res(s[2 * ks][0], s[2 * ks][1], pha[0]);
            pla[1] = pack_bf2_res(s[2 * ks][2], s[2 * ks][3], pha[1]);
            pla[2] = pack_bf2_res(s[2 * ks + 1][0], s[2 * ks + 1][1], pha[2]);
            pla[3] = pack_bf2_res(s[2 * ks + 1][2], s[2 * ks + 1][3], pha[3]);
#pragma unroll
            for (int gr = 0; gr < 8; gr++) {
                uint32_t vh4[4], vl4[4];
                uint32_t ro = st + 2 * KVT + (ks * 16 + arow) * ARB +
                              gr * 32 + vcolB;
                ldsm4t(vh4[0], vh4[1], vh4[2], vh4[3], ro);
                ldsm4t(vl4[0], vl4[1], vl4[2], vl4[3], ro + KVT);
                mma_bf16(o[2 * gr], pha, vh4);
                mma_bf16(o[2 * gr], pha, vl4);
                mma_bf16(o[2 * gr], pla, vh4);
                mma_bf16(o[2 * gr + 1], pha, vh4 + 2);
                mma_bf16(o[2 * gr + 1], pha, vl4 + 2);
                mma_bf16(o[2 * gr + 1], pla, vh4 + 2);
            }
        }
        __syncthreads();
        if (t + 2 < NT) load_stage(t & 1, t + 2);
    }

    // ---- epilogue: normalize, split hi/lo, write g_Xhi/g_Xlo [b][s][h*d] ----
    float inv0 = 1.f / l0, inv1 = 1.f / l1;
    const int r0 = qt * 128 + wm + g, r1 = r0 + 8;
#pragma unroll
    for (int j = 0; j < 16; j++) {
        int col = h * 128 + j * 8 + 2 * t4;
        float a0 = o[j][0] * inv0, a1 = o[j][1] * inv0;
        float b0 = o[j][2] * inv1, b1 = o[j][3] * inv1;
        size_t i0 = ((size_t)(b * Sn + r0)) * 4096 + col;
        size_t i1 = ((size_t)(b * Sn + r1)) * 4096 + col;
        uint32_t h0 = pack_bf2(a0, a1);
        uint32_t h1 = pack_bf2(b0, b1);
        *reinterpret_cast<uint32_t*>(&g_Xhi[i0]) = h0;
        *reinterpret_cast<uint32_t*>(&g_Xlo[i0]) = pack_bf2_res(a0, a1, h0);
        *reinterpret_cast<uint32_t*>(&g_Xhi[i1]) = h1;
        *reinterpret_cast<uint32_t*>(&g_Xlo[i1]) = pack_bf2_res(b0, b1, h1);
    }
}

// ---------------------------------------------------------------------------
extern "C" void kernel_launch(void* const* d_in, const int* in_sizes, int n_in,
                              void* d_out, int out_size)
{
    const float* hidden = (const float*)d_in[0];
    const float* Wq = (const float*)d_in[2];
    const float* Wk = (const float*)d_in[3];
    const float* Wv = (const float*)d_in[4];
    const float* Wo = (const float*)d_in[5];
    float* out = (float*)d_out;

    __nv_bfloat16 *pXh, *pXl, *pQTh, *pQTl, *pKTh, *pKTl, *pVTh, *pVTl, *pOTh, *pOTl;
    __nv_bfloat16 *pQh, *pQl, *pKh, *pKl, *pVh, *pVl;
    cudaGetSymbolAddress((void**)&pXh, g_Xhi);
    cudaGetSymbolAddress((void**)&pXl, g_Xlo);
    cudaGetSymbolAddress((void**)&pQTh, g_WqThi);
    cudaGetSymbolAddress((void**)&pQTl, g_WqTlo);
    cudaGetSymbolAddress((void**)&pKTh, g_WkThi);
    cudaGetSymbolAddress((void**)&pKTl, g_WkTlo);
    cudaGetSymbolAddress((void**)&pVTh, g_WvThi);
    cudaGetSymbolAddress((void**)&pVTl, g_WvTlo);
    cudaGetSymbolAddress((void**)&pOTh, g_WoThi);
    cudaGetSymbolAddress((void**)&pOTl, g_WoTlo);
    cudaGetSymbolAddress((void**)&pQh, g_Qh);
    cudaGetSymbolAddress((void**)&pQl, g_Ql);
    cudaGetSymbolAddress((void**)&pKh, g_Kh);
    cudaGetSymbolAddress((void**)&pKl, g_Kl);
    cudaGetSymbolAddress((void**)&pVh, g_Vh);
    cudaGetSymbolAddress((void**)&pVl, g_Vl);

    cudaFuncSetAttribute(hgemm_kernel<0>,
                         cudaFuncAttributeMaxDynamicSharedMemorySize, HG_SMEM);
    cudaFuncSetAttribute(hgemm_kernel<1>,
                         cudaFuncAttributeMaxDynamicSharedMemorySize, HG_SMEM);
    cudaFuncSetAttribute(hgemm_kernel<2>,
                         cudaFuncAttributeMaxDynamicSharedMemorySize, HG_SMEM);
    cudaFuncSetAttribute(hgemm_kernel<3>,
                         cudaFuncAttributeMaxDynamicSharedMemorySize, HG_SMEM);
    cudaFuncSetAttribute(attn_mma_kernel,
                         cudaFuncAttributeMaxDynamicSharedMemorySize, AT_SMEM);

    // 0) conversions + RoPE table
    const int n4x = Mn * Hn / 4;
    split_kernel<<<n4x / 256, 256>>>(hidden, pXh, pXl, n4x);
    dim3 tb(32, 8);
    tsplit_kernel<<<dim3(4096 / 32, 4096 / 32), tb>>>(Wq, pQTh, pQTl, Hn, 4096);
    tsplit_kernel<<<dim3(1024 / 32, 4096 / 32), tb>>>(Wk, pKTh, pKTl, Hn, 1024);
    tsplit_kernel<<<dim3(1024 / 32, 4096 / 32), tb>>>(Wv, pVTh, pVTl, Hn, 1024);
    tsplit_kernel<<<dim3(4096 / 32, 4096 / 32), tb>>>(Wo, pOTh, pOTl, 4096, Hn);
    ropetab_kernel<<<Sn * 64 / 256, 256>>>();

    // 1) projections with fused RoPE/split epilogues
    hgemm_kernel<1><<<dim3(4096 / 128, Mn / 128), 256, HG_SMEM>>>(
        pXh, pXl, pQTh, pQTl, nullptr, pQh, pQl, 4096, Hn);
    hgemm_kernel<2><<<dim3(1024 / 128, Mn / 128), 256, HG_SMEM>>>(
        pXh, pXl, pKTh, pKTl, nullptr, pKh, pKl, 1024, Hn);
    hgemm_kernel<3><<<dim3(1024 / 128, Mn / 128), 256, HG_SMEM>>>(
        pXh, pXl, pVTh, pVTl, nullptr, pVh, pVl, 1024, Hn);

    // 2) causal flash attention (writes hi/lo into g_Xhi/g_Xlo)
    dim3 ga(Sn / 128, NHn, Bn);
    attn_mma_kernel<<<ga, 256, AT_SMEM>>>();

    // 3) output projection
    hgemm_kernel<0><<<dim3(4096 / 128, Mn / 128), 256, HG_SMEM>>>(
        pXh, pXl, pOTh, pOTl, out, nullptr, nullptr, 4096, Hn);
}

// round 8
// speedup vs baseline: 1.0137x; 1.0137x over previous
#include <cuda_runtime.h>
#include <cuda_bf16.h>
#include <math.h>
#include <stdint.h>

// Problem dims
constexpr int Bn = 2, Sn = 2048, Hn = 4096, NHn = 32, NKVn = 8, HDn = 128;
constexpr int Mn = Bn * Sn;
constexpr float QK_SCALE = 0.08838834764831845f; // 1/sqrt(128)
constexpr float L2E = 1.4426950408889634f;

// bf16 split scratch
__device__ __nv_bfloat16 g_Xhi[(size_t)Mn * Hn];   // X split; reused for attn out
__device__ __nv_bfloat16 g_Xlo[(size_t)Mn * Hn];
__device__ __nv_bfloat16 g_WqThi[(size_t)4096 * 4096];
__device__ __nv_bfloat16 g_WqTlo[(size_t)4096 * 4096];
__device__ __nv_bfloat16 g_WkThi[(size_t)1024 * 4096];
__device__ __nv_bfloat16 g_WkTlo[(size_t)1024 * 4096];
__device__ __nv_bfloat16 g_WvThi[(size_t)1024 * 4096];
__device__ __nv_bfloat16 g_WvTlo[(size_t)1024 * 4096];
__device__ __nv_bfloat16 g_WoThi[(size_t)4096 * 4096];
__device__ __nv_bfloat16 g_WoTlo[(size_t)4096 * 4096];
// attention operands (hi/lo, post-RoPE), written by GEMM epilogues
__device__ __nv_bfloat16 g_Qh[(size_t)Bn * NHn * Sn * HDn];
__device__ __nv_bfloat16 g_Ql[(size_t)Bn * NHn * Sn * HDn];
__device__ __nv_bfloat16 g_Kh[(size_t)Bn * NKVn * Sn * HDn];
__device__ __nv_bfloat16 g_Kl[(size_t)Bn * NKVn * Sn * HDn];
__device__ __nv_bfloat16 g_Vh[(size_t)Bn * NKVn * Sn * HDn];
__device__ __nv_bfloat16 g_Vl[(size_t)Bn * NKVn * Sn * HDn];
// RoPE cos/sin table [s][d<64]
__device__ float2 g_RT[(size_t)Sn * 64];

// ---------------------------------------------------------------------------
// helpers
// ---------------------------------------------------------------------------
__device__ __forceinline__ uint32_t smem_u32(const void* p) {
    uint32_t a;
    asm("{ .reg .u64 t; cvta.to.shared.u64 t, %1; cvt.u32.u64 %0, t; }"
        : "=r"(a) : "l"(p));
    return a;
}
__device__ __forceinline__ void cpa16(uint32_t dst, const void* src) {
    asm volatile("cp.async.cg.shared.global [%0], [%1], 16;"
                 :: "r"(dst), "l"(src) : "memory");
}
__device__ __forceinline__ void ldsm4(uint32_t& r0, uint32_t& r1,
                                      uint32_t& r2, uint32_t& r3, uint32_t a) {
    asm volatile("ldmatrix.sync.aligned.m8n8.x4.shared.b16 {%0,%1,%2,%3}, [%4];"
                 : "=r"(r0), "=r"(r1), "=r"(r2), "=r"(r3) : "r"(a));
}
__device__ __forceinline__ void ldsm4t(uint32_t& r0, uint32_t& r1,
                                       uint32_t& r2, uint32_t& r3, uint32_t a) {
    asm volatile("ldmatrix.sync.aligned.m8n8.x4.trans.shared.b16 {%0,%1,%2,%3}, [%4];"
                 : "=r"(r0), "=r"(r1), "=r"(r2), "=r"(r3) : "r"(a));
}
__device__ __forceinline__ void mma_bf16(float* c, const uint32_t* a,
                                         const uint32_t* b) {
    asm volatile(
        "mma.sync.aligned.m16n8k16.row.col.f32.bf16.bf16.f32 "
        "{%0,%1,%2,%3}, {%4,%5,%6,%7}, {%8,%9}, {%0,%1,%2,%3};"
        : "+f"(c[0]), "+f"(c[1]), "+f"(c[2]), "+f"(c[3])
        : "r"(a[0]), "r"(a[1]), "r"(a[2]), "r"(a[3]), "r"(b[0]), "r"(b[1]));
}
// fast exp2 on the FMA pipe (y <= 0; clamp makes masked rows vanish)
__device__ __forceinline__ float fexp2(float y) {
    y = fmaxf(y, -126.f);
    float fl = floorf(y);
    float f = y - fl;
    float p = 1.8775767e-3f;
    p = fmaf(p, f, 8.9893397e-3f);
    p = fmaf(p, f, 5.5826318e-2f);
    p = fmaf(p, f, 2.4015361e-1f);
    p = fmaf(p, f, 6.9315308e-1f);
    p = fmaf(p, f, 9.9999994e-1f);
    return __int_as_float(((int)fl + 127) << 23) * p;
}
__device__ __forceinline__ uint32_t pack_bf2(float a, float b) {
    __nv_bfloat162 v = __floats2bfloat162_rn(a, b);
    return *reinterpret_cast<uint32_t*>(&v);
}
__device__ __forceinline__ uint32_t pack_bf2_res(float a, float b, uint32_t hi) {
    __nv_bfloat162 hv = *reinterpret_cast<__nv_bfloat162*>(&hi);
    return pack_bf2(a - __bfloat162float(hv.x), b - __bfloat162float(hv.y));
}

// ---------------------------------------------------------------------------
// RoPE table (accurate powf + sincosf, computed once; pos == s)
// ---------------------------------------------------------------------------
__global__ void ropetab_kernel()
{
    int idx = blockIdx.x * 256 + threadIdx.x;   // Sn*64 = 131072
    int s = idx >> 6, d = idx & 63;
    float inv = powf(10000.f, -(float)d / 64.f);
    float sn, cs;
    sincosf((float)s * inv, &sn, &cs);
    g_RT[idx] = make_float2(cs, sn);
}

// ---------------------------------------------------------------------------
// Split conversion: x -> (hi, lo) bf16
// ---------------------------------------------------------------------------
__global__ void split_kernel(const float* __restrict__ x,
                             __nv_bfloat16* __restrict__ hi,
                             __nv_bfloat16* __restrict__ lo, int n4)
{
    int i = blockIdx.x * 256 + threadIdx.x;
    if (i >= n4) return;
    float4 v = reinterpret_cast<const float4*>(x)[i];
    __nv_bfloat16 h0 = __float2bfloat16(v.x), h1 = __float2bfloat16(v.y);
    __nv_bfloat16 h2 = __float2bfloat16(v.z), h3 = __float2bfloat16(v.w);
    __nv_bfloat16 l0 = __float2bfloat16(v.x - __bfloat162float(h0));
    __nv_bfloat16 l1 = __float2bfloat16(v.y - __bfloat162float(h1));
    __nv_bfloat16 l2 = __float2bfloat16(v.z - __bfloat162float(h2));
    __nv_bfloat16 l3 = __float2bfloat16(v.w - __bfloat162float(h3));
    reinterpret_cast<__nv_bfloat162*>(hi)[i * 2 + 0] = __halves2bfloat162(h0, h1);
    reinterpret_cast<__nv_bfloat162*>(hi)[i * 2 + 1] = __halves2bfloat162(h2, h3);
    reinterpret_cast<__nv_bfloat162*>(lo)[i * 2 + 0] = __halves2bfloat162(l0, l1);
    reinterpret_cast<__nv_bfloat162*>(lo)[i * 2 + 1] = __halves2bfloat162(l2, l3);
}

// ---------------------------------------------------------------------------
// Transpose + split: W[K][N] fp32 -> T{hi,lo}[N][K] bf16
// ---------------------------------------------------------------------------
__global__ void tsplit_kernel(const float* __restrict__ W,
                              __nv_bfloat16* __restrict__ Thi,
                              __nv_bfloat16* __restrict__ Tlo, int K, int N)
{
    __shared__ float t[32][33];
    int tx = threadIdx.x, ty = threadIdx.y;
    int bx = blockIdx.x, by = blockIdx.y;
#pragma unroll
    for (int i = 0; i < 4; i++) {
        int r = by * 32 + ty + i * 8;
        t[ty + i * 8][tx] = W[(size_t)r * N + bx * 32 + tx];
    }
    __syncthreads();
#pragma unroll
    for (int i = 0; i < 4; i++) {
        int n = bx * 32 + ty + i * 8;
        int k = by * 32 + tx;
        float v = t[tx][ty + i * 8];
        __nv_bfloat16 h = __float2bfloat16(v);
        __nv_bfloat16 l = __float2bfloat16(v - __bfloat162float(h));
        Thi[(size_t)n * K + k] = h;
        Tlo[(size_t)n * K + k] = l;
    }
}

// ---------------------------------------------------------------------------
// bf16 split GEMM on mma.sync, 3-stage cp.async pipeline:
// MODE 0: fp32 C row-major (output projection -> d_out)
// MODE 1: RoPE + split -> Oh/Ol in Q layout [b][h][s][d], scale=QK_SCALE
// MODE 2: RoPE + split -> Oh/Ol in KV layout, scale=1
// MODE 3: split only   -> Oh/Ol in KV layout (V)
// ---------------------------------------------------------------------------
constexpr int TROW = 144;
constexpr int TTILE = 128 * TROW;
constexpr int TSTAGE = 4 * TTILE;        // 73728 B
constexpr int HG_SMEM = 3 * TSTAGE;      // 221184 B (3-stage)

template <int MODE>
__global__ __launch_bounds__(256) void hgemm_kernel(
    const __nv_bfloat16* __restrict__ Ahi, const __nv_bfloat16* __restrict__ Alo,
    const __nv_bfloat16* __restrict__ Bhi, const __nv_bfloat16* __restrict__ Blo,
    float* __restrict__ C,
    __nv_bfloat16* __restrict__ Oh, __nv_bfloat16* __restrict__ Ol,
    int N, int K)
{
    extern __shared__ char smem[];
    const uint32_t sb = smem_u32(smem);

    const int tid = threadIdx.x;
    const int wid = tid >> 5, lane = tid & 31;
    const int g = lane >> 2, t4 = lane & 3;
    const int wr = wid >> 2, wc = wid & 3;
    const int wm = wr * 64, wn = wc * 32;
    const int m0 = blockIdx.y * 128, n0 = blockIdx.x * 128;

    const __nv_bfloat16* Ah = Ahi + (size_t)m0 * K;
    const __nv_bfloat16* Al = Alo + (size_t)m0 * K;
    const __nv_bfloat16* Bh = Bhi + (size_t)n0 * K;
    const __nv_bfloat16* Bl = Blo + (size_t)n0 * K;

    float c[4][4][4];
#pragma unroll
    for (int mi = 0; mi < 4; mi++)
#pragma unroll
        for (int ni = 0; ni < 4; ni++)
#pragma unroll
            for (int r = 0; r < 4; r++) c[mi][ni][r] = 0.f;

    const int rb = tid >> 3;
    const int c8 = tid & 7;

    auto load_chunk = [&](int stage, int koff) {
        const uint32_t base = sb + stage * TSTAGE;
#pragma unroll
        for (int i = 0; i < 16; i++) {
            const int tile = i >> 2;
            const int r = (i & 3) * 32 + rb;
            const __nv_bfloat16* s =
                (tile == 0) ? Ah : (tile == 1) ? Al : (tile == 2) ? Bh : Bl;
            cpa16(base + tile * TTILE + r * TROW + c8 * 16,
                  s + (size_t)r * K + koff + c8 * 8);
        }
        asm volatile("cp.async.commit_group;" ::: "memory");
    };

    const int NC = K / 64;
    load_chunk(0, 0);
    if (NC > 1) load_chunk(1, 64);

    const int arow_off = (lane & 7) + ((lane >> 3) & 1) * 8;
    const int acol_off = (lane >> 4) * 8;
    const int brow_off = (lane & 7) + (lane >> 4) * 8;
    const int bcol_off = ((lane >> 3) & 1) * 8;

    for (int ch = 0; ch < NC; ch++) {
        if (ch + 1 < NC)
            asm volatile("cp.async.wait_group 1;" ::: "memory");
        else
            asm volatile("cp.async.wait_group 0;" ::: "memory");
        __syncthreads();
        // issue chunk ch+2 BEFORE compute: 2 chunks in flight during compute
        if (ch + 2 < NC) load_chunk((ch + 2) % 3, (ch + 2) * 64);

        const uint32_t st = sb + (ch % 3) * TSTAGE;
        const uint32_t ah_b = st, al_b = st + TTILE;
        const uint32_t bh_b = st + 2 * TTILE, bl_b = st + 3 * TTILE;

#pragma unroll
        for (int kk = 0; kk < 64; kk += 16) {
            uint32_t fah[4][4], fal[4][4], fbh[4][2], fbl[4][2];
#pragma unroll
            for (int mi = 0; mi < 4; mi++) {
                const uint32_t ro = (wm + mi * 16 + arow_off) * TROW +
                                    (kk + acol_off) * 2;
                ldsm4(fah[mi][0], fah[mi][1], fah[mi][2], fah[mi][3], ah_b + ro);
                ldsm4(fal[mi][0], fal[mi][1], fal[mi][2], fal[mi][3], al_b + ro);
            }
#pragma unroll
            for (int bt = 0; bt < 2; bt++) {
                const uint32_t ro = (wn + bt * 16 + brow_off) * TROW +
                                    (kk + bcol_off) * 2;
                ldsm4(fbh[2 * bt][0], fbh[2 * bt][1],
                      fbh[2 * bt + 1][0], fbh[2 * bt + 1][1], bh_b + ro);
                ldsm4(fbl[2 * bt][0], fbl[2 * bt][1],
                      fbl[2 * bt + 1][0], fbl[2 * bt + 1][1], bl_b + ro);
            }
#pragma unroll
            for (int mi = 0; mi < 4; mi++)
#pragma unroll
                for (int ni = 0; ni < 4; ni++) {
                    mma_bf16(c[mi][ni], fah[mi], fbh[ni]);
                    mma_bf16(c[mi][ni], fah[mi], fbl[ni]);
                    mma_bf16(c[mi][ni], fal[mi], fbh[ni]);
                }
        }
    }

    if (MODE == 0) {
#pragma unroll
        for (int mi = 0; mi < 4; mi++)
#pragma unroll
            for (int ni = 0; ni < 4; ni++) {
                const int row0 = m0 + wm + mi * 16 + g;
                const int col = n0 + wn + ni * 8 + 2 * t4;
#pragma unroll
                for (int half = 0; half < 2; half++) {
                    const int m = row0 + half * 8;
                    float2 v = half ? make_float2(c[mi][ni][2], c[mi][ni][3])
                                    : make_float2(c[mi][ni][0], c[mi][ni][1]);
                    *reinterpret_cast<float2*>(&C[(size_t)m * N + col]) = v;
                }
            }
    } else if (MODE == 3) {
        const int hh = n0 >> 7;
#pragma unroll
        for (int mi = 0; mi < 4; mi++)
#pragma unroll
            for (int ni = 0; ni < 4; ni++) {
                const int row0 = m0 + wm + mi * 16 + g;
                const int col = wn + ni * 8 + 2 * t4;
#pragma unroll
                for (int half = 0; half < 2; half++) {
                    const int m = row0 + half * 8;
                    float v0 = half ? c[mi][ni][2] : c[mi][ni][0];
                    float v1 = half ? c[mi][ni][3] : c[mi][ni][1];
                    const int bb = m >> 11, s = m & 2047;
                    size_t base =
                        (((size_t)(bb * NKVn + hh) * Sn) + s) * HDn + col;
                    uint32_t hv = pack_bf2(v0, v1);
                    *reinterpret_cast<uint32_t*>(&Oh[base]) = hv;
                    *reinterpret_cast<uint32_t*>(&Ol[base]) =
                        pack_bf2_res(v0, v1, hv);
                }
            }
    } else {
        // MODE 1/2: stage tile to smem, apply RoPE pairing (d, d+64), split.
        // Staging overlays stage 0 which the last chunk may have used -> sync.
        __syncthreads();
        float* stg = reinterpret_cast<float*>(smem);
#pragma unroll
        for (int mi = 0; mi < 4; mi++)
#pragma unroll
            for (int ni = 0; ni < 4; ni++) {
                const int rl = wm + mi * 16 + g;
                const int cl = wn + ni * 8 + 2 * t4;
                stg[rl * 132 + cl] = c[mi][ni][0];
                stg[rl * 132 + cl + 1] = c[mi][ni][1];
                stg[(rl + 8) * 132 + cl] = c[mi][ni][2];
                stg[(rl + 8) * 132 + cl + 1] = c[mi][ni][3];
            }
        __syncthreads();
        const int heads = (MODE == 1) ? NHn : NKVn;
        const float scale = (MODE == 1) ? QK_SCALE : 1.f;
        const int hh = n0 >> 7;
#pragma unroll
        for (int i = 0; i < 32; i++) {
            int p = tid + i * 256;          // 8192 pairs
            int r = p >> 6, d = p & 63;
            int m = m0 + r;
            int bb = m >> 11, s = m & 2047;
            float x0 = stg[r * 132 + d];
            float x1 = stg[r * 132 + d + 64];
            float2 t = g_RT[s * 64 + d];
            float r0 = (x0 * t.x - x1 * t.y) * scale;
            float r1 = (x1 * t.x + x0 * t.y) * scale;
            __nv_bfloat16 h0 = __float2bfloat16(r0);
            __nv_bfloat16 h1 = __float2bfloat16(r1);
            size_t base = (((size_t)(bb * heads + hh) * Sn) + s) * HDn;
            Oh[base + d] = h0;
            Oh[base + d + 64] = h1;
            Ol[base + d] = __float2bfloat16(r0 - __bfloat162float(h0));
            Ol[base + d + 64] = __float2bfloat16(r1 - __bfloat162float(h1));
        }
    }
}

// ---------------------------------------------------------------------------
// Flash attention on mma.sync, bf16 split, BQ=128, BK=64, 8 warps,
// 3-stage cp.async pipeline. Output hi/lo bf16 into g_Xhi/g_Xlo.
// ---------------------------------------------------------------------------
constexpr int ARB = 272;                  // padded row bytes (136 bf16)
constexpr int KVT = 64 * ARB;             // one 64x128 bf16 tile = 17408 B
constexpr int ASTG = 4 * KVT;             // Kh,Kl,Vh,Vl per stage = 69632 B
constexpr int AT_SMEM = 3 * ASTG;         // 208896 B (3-stage)

__global__ __launch_bounds__(256, 1) void attn_mma_kernel()
{
    extern __shared__ char smem[];
    const uint32_t sb = smem_u32(smem);
    const int qt = blockIdx.x, h = blockIdx.y, b = blockIdx.z;
    const int tid = threadIdx.x, wid = tid >> 5, lane = tid & 31;
    const int g = lane >> 2, t4 = lane & 3;
    const int wm = wid * 16;
    const int kvh = h >> 2;
    const int NT = 2 * (qt + 1);

    const __nv_bfloat16* Qhp = g_Qh + ((size_t)(b * NHn + h) * Sn + qt * 128) * HDn;
    const __nv_bfloat16* Qlp = g_Ql + ((size_t)(b * NHn + h) * Sn + qt * 128) * HDn;
    const __nv_bfloat16* Khp = g_Kh + ((size_t)(b * NKVn + kvh) * Sn) * HDn;
    const __nv_bfloat16* Klp = g_Kl + ((size_t)(b * NKVn + kvh) * Sn) * HDn;
    const __nv_bfloat16* Vhp = g_Vh + ((size_t)(b * NKVn + kvh) * Sn) * HDn;
    const __nv_bfloat16* Vlp = g_Vl + ((size_t)(b * NKVn + kvh) * Sn) * HDn;

    // Q tiles -> stage 2 region (first overwritten by KV chunk 2, which is
    // issued only after Q fragments are extracted)
    const uint32_t qhb = sb + 2 * ASTG, qlb = sb + 2 * ASTG + 34816;
#pragma unroll
    for (int i = 0; i < 8; i++) {
        int id = tid + i * 256, r = id >> 4, c = id & 15;
        cpa16(qhb + r * ARB + c * 16, Qhp + r * HDn + c * 8);
        cpa16(qlb + r * ARB + c * 16, Qlp + r * HDn + c * 8);
    }
    asm volatile("cp.async.commit_group;" ::: "memory");

    auto load_stage = [&](int stg, int t) {
        const uint32_t st = sb + stg * ASTG;
        const __nv_bfloat16* kh = Khp + (size_t)t * 64 * HDn;
        const __nv_bfloat16* kl = Klp + (size_t)t * 64 * HDn;
        const __nv_bfloat16* vh = Vhp + (size_t)t * 64 * HDn;
        const __nv_bfloat16* vl = Vlp + (size_t)t * 64 * HDn;
#pragma unroll
        for (int i = 0; i < 4; i++) {
            int id = tid + i * 256, r = id >> 4, c = id & 15;
            cpa16(st + 0 * KVT + r * ARB + c * 16, kh + r * HDn + c * 8);
            cpa16(st + 1 * KVT + r * ARB + c * 16, kl + r * HDn + c * 8);
            cpa16(st + 2 * KVT + r * ARB + c * 16, vh + r * HDn + c * 8);
            cpa16(st + 3 * KVT + r * ARB + c * 16, vl + r * HDn + c * 8);
        }
        asm volatile("cp.async.commit_group;" ::: "memory");
    };
    load_stage(0, 0);

    asm volatile("cp.async.wait_group 1;" ::: "memory");  // Q arrived
    __syncthreads();

    const int arow = (lane & 7) + ((lane >> 3) & 1) * 8;
    const int acolB = (lane >> 4) * 16;
    uint32_t qhf[8][4], qlf[8][4];
#pragma unroll
    for (int ks = 0; ks < 8; ks++) {
        uint32_t ro = (wm + arow) * ARB + ks * 32 + acolB;
        ldsm4(qhf[ks][0], qhf[ks][1], qhf[ks][2], qhf[ks][3], qhb + ro);
        ldsm4(qlf[ks][0], qlf[ks][1], qlf[ks][2], qlf[ks][3], qlb + ro);
    }
    __syncthreads();          // Q smem region free before chunk 2 overwrites
    if (1 < NT) load_stage(1, 1);

    float o[16][4];
#pragma unroll
    for (int j = 0; j < 16; j++)
#pragma unroll
        for (int e = 0; e < 4; e++) o[j][e] = 0.f;
    float m0 = -1e30f, m1 = -1e30f, l0 = 0.f, l1 = 0.f;

    const int brow = (lane & 7) + (lane >> 4) * 8;
    const int bcolB = ((lane >> 3) & 1) * 16;
    const int vcolB = (lane >> 4) * 16;
    const int row0g = qt * 128 + wm + g;

    for (int t = 0; t < NT; t++) {
        if (t + 1 < NT)
            asm volatile("cp.async.wait_group 1;" ::: "memory");
        else
            asm volatile("cp.async.wait_group 0;" ::: "memory");
        __syncthreads();
        if (t + 2 < NT) load_stage((t + 2) % 3, t + 2);
        const uint32_t st = sb + (t % 3) * ASTG;

        // ---- scores S = Q K^T (3-pass split) ----
        float s[8][4];
#pragma unroll
        for (int j = 0; j < 8; j++)
#pragma unroll
            for (int e = 0; e < 4; e++) s[j][e] = 0.f;

#pragma unroll
        for (int ks = 0; ks < 8; ks++) {
#pragma unroll
            for (int gr = 0; gr < 4; gr++) {
                uint32_t kh4[4], kl4[4];
                uint32_t ro = st + (gr * 16 + brow) * ARB + ks * 32 + bcolB;
                ldsm4(kh4[0], kh4[1], kh4[2], kh4[3], ro);
                ldsm4(kl4[0], kl4[1], kl4[2], kl4[3], ro + KVT);
                mma_bf16(s[2 * gr], qhf[ks], kh4);
                mma_bf16(s[2 * gr], qhf[ks], kl4);
                mma_bf16(s[2 * gr], qlf[ks], kh4);
                mma_bf16(s[2 * gr + 1], qhf[ks], kh4 + 2);
                mma_bf16(s[2 * gr + 1], qhf[ks], kl4 + 2);
                mma_bf16(s[2 * gr + 1], qlf[ks], kh4 + 2);
            }
        }

        // ---- causal mask ----
        if (t >= 2 * qt) {
#pragma unroll
            for (int j = 0; j < 8; j++) {
                int c0 = t * 64 + j * 8 + 2 * t4;
                if (c0 > row0g)     s[j][0] = -1e30f;
                if (c0 + 1 > row0g) s[j][1] = -1e30f;
                if (c0 > row0g + 8)     s[j][2] = -1e30f;
                if (c0 + 1 > row0g + 8) s[j][3] = -1e30f;
            }
        }

        // ---- online softmax ----
        float tm0 = -1e30f, tm1 = -1e30f;
#pragma unroll
        for (int j = 0; j < 8; j++) {
            tm0 = fmaxf(tm0, fmaxf(s[j][0], s[j][1]));
            tm1 = fmaxf(tm1, fmaxf(s[j][2], s[j][3]));
        }
        tm0 = fmaxf(tm0, __shfl_xor_sync(0xffffffffu, tm0, 1));
        tm0 = fmaxf(tm0, __shfl_xor_sync(0xffffffffu, tm0, 2));
        tm1 = fmaxf(tm1, __shfl_xor_sync(0xffffffffu, tm1, 1));
        tm1 = fmaxf(tm1, __shfl_xor_sync(0xffffffffu, tm1, 2));
        float mn0 = fmaxf(m0, tm0), mn1 = fmaxf(m1, tm1);
        float cor0 = fexp2((m0 - mn0) * L2E);
        float cor1 = fexp2((m1 - mn1) * L2E);
        m0 = mn0; m1 = mn1;
#pragma unroll
        for (int j = 0; j < 16; j++) {
            o[j][0] *= cor0; o[j][1] *= cor0;
            o[j][2] *= cor1; o[j][3] *= cor1;
        }
        float rs0 = 0.f, rs1 = 0.f;
#pragma unroll
        for (int j = 0; j < 8; j++) {
            s[j][0] = fexp2((s[j][0] - mn0) * L2E);
            s[j][1] = fexp2((s[j][1] - mn0) * L2E);
            s[j][2] = fexp2((s[j][2] - mn1) * L2E);
            s[j][3] = fexp2((s[j][3] - mn1) * L2E);
            rs0 += s[j][0] + s[j][1];
            rs1 += s[j][2] + s[j][3];
        }
        rs0 += __shfl_xor_sync(0xffffffffu, rs0, 1);
        rs0 += __shfl_xor_sync(0xffffffffu, rs0, 2);
        rs1 += __shfl_xor_sync(0xffffffffu, rs1, 1);
        rs1 += __shfl_xor_sync(0xffffffffu, rs1, 2);
        l0 = l0 * cor0 + rs0;
        l1 = l1 * cor1 + rs1;

        // ---- O += P V ----
#pragma unroll
        for (int ks = 0; ks < 4; ks++) {
            uint32_t pha[4], pla[4];
            pha[0] = pack_bf2(s[2 * ks][0], s[2 * ks][1]);
            pha[1] = pack_bf2(s[2 * ks][2], s[2 * ks][3]);
            pha[2] = pack_bf2(s[2 * ks + 1][0], s[2 * ks + 1][1]);
            pha[3] = pack_bf2(s[2 * ks + 1][2], s[2 * ks + 1][3]);
            pla[0] = pack_bf2_res(s[2 * ks][0], s[2 * ks][1], pha[0]);
            pla[1] = pack_bf2_res(s[2 * ks][2], s[2 * ks][3], pha[1]);
            pla[2] = pack_bf2_res(s[2 * ks + 1][0], s[2 * ks + 1][1], pha[2]);
            pla[3] = pack_bf2_res(s[2 * ks + 1][2], s[2 * ks + 1][3], pha[3]);
#pragma unroll
            for (int gr = 0; gr < 8; gr++) {
                uint32_t vh4[4], vl4[4];
                uint32_t ro = st + 2 * KVT + (ks * 16 + arow) * ARB +
                              gr * 32 + vcolB;
                ldsm4t(vh4[0], vh4[1], vh4[2], vh4[3], ro);
                ldsm4t(vl4[0], vl4[1], vl4[2], vl4[3], ro + KVT);
                mma_bf16(o[2 * gr], pha, vh4);
                mma_bf16(o[2 * gr], pha, vl4);
                mma_bf16(o[2 * gr], pla, vh4);
                mma_bf16(o[2 * gr + 1], pha, vh4 + 2);
                mma_bf16(o[2 * gr + 1], pha, vl4 + 2);
                mma_bf16(o[2 * gr + 1], pla, vh4 + 2);
            }
        }
    }

    // ---- epilogue: normalize, split hi/lo, write g_Xhi/g_Xlo [b][s][h*d] ----
    float inv0 = 1.f / l0, inv1 = 1.f / l1;
    const int r0 = qt * 128 + wm + g, r1 = r0 + 8;
#pragma unroll
    for (int j = 0; j < 16; j++) {
        int col = h * 128 + j * 8 + 2 * t4;
        float a0 = o[j][0] * inv0, a1 = o[j][1] * inv0;
        float b0 = o[j][2] * inv1, b1 = o[j][3] * inv1;
        size_t i0 = ((size_t)(b * Sn + r0)) * 4096 + col;
        size_t i1 = ((size_t)(b * Sn + r1)) * 4096 + col;
        uint32_t h0 = pack_bf2(a0, a1);
        uint32_t h1 = pack_bf2(b0, b1);
        *reinterpret_cast<uint32_t*>(&g_Xhi[i0]) = h0;
        *reinterpret_cast<uint32_t*>(&g_Xlo[i0]) = pack_bf2_res(a0, a1, h0);
        *reinterpret_cast<uint32_t*>(&g_Xhi[i1]) = h1;
        *reinterpret_cast<uint32_t*>(&g_Xlo[i1]) = pack_bf2_res(b0, b1, h1);
    }
}

// ---------------------------------------------------------------------------
extern "C" void kernel_launch(void* const* d_in, const int* in_sizes, int n_in,
                              void* d_out, int out_size)
{
    const float* hidden = (const float*)d_in[0];
    const float* Wq = (const float*)d_in[2];
    const float* Wk = (const float*)d_in[3];
    const float* Wv = (const float*)d_in[4];
    const float* Wo = (const float*)d_in[5];
    float* out = (float*)d_out;

    __nv_bfloat16 *pXh, *pXl, *pQTh, *pQTl, *pKTh, *pKTl, *pVTh, *pVTl, *pOTh, *pOTl;
    __nv_bfloat16 *pQh, *pQl, *pKh, *pKl, *pVh, *pVl;
    cudaGetSymbolAddress((void**)&pXh, g_Xhi);
    cudaGetSymbolAddress((void**)&pXl, g_Xlo);
    cudaGetSymbolAddress((void**)&pQTh, g_WqThi);
    cudaGetSymbolAddress((void**)&pQTl, g_WqTlo);
    cudaGetSymbolAddress((void**)&pKTh, g_WkThi);
    cudaGetSymbolAddress((void**)&pKTl, g_WkTlo);
    cudaGetSymbolAddress((void**)&pVTh, g_WvThi);
    cudaGetSymbolAddress((void**)&pVTl, g_WvTlo);
    cudaGetSymbolAddress((void**)&pOTh, g_WoThi);
    cudaGetSymbolAddress((void**)&pOTl, g_WoTlo);
    cudaGetSymbolAddress((void**)&pQh, g_Qh);
    cudaGetSymbolAddress((void**)&pQl, g_Ql);
    cudaGetSymbolAddress((void**)&pKh, g_Kh);
    cudaGetSymbolAddress((void**)&pKl, g_Kl);
    cudaGetSymbolAddress((void**)&pVh, g_Vh);
    cudaGetSymbolAddress((void**)&pVl, g_Vl);

    cudaFuncSetAttribute(hgemm_kernel<0>,
                         cudaFuncAttributeMaxDynamicSharedMemorySize, HG_SMEM);
    cudaFuncSetAttribute(hgemm_kernel<1>,
                         cudaFuncAttributeMaxDynamicSharedMemorySize, HG_SMEM);
    cudaFuncSetAttribute(hgemm_kernel<2>,
                         cudaFuncAttributeMaxDynamicSharedMemorySize, HG_SMEM);
    cudaFuncSetAttribute(hgemm_kernel<3>,
                         cudaFuncAttributeMaxDynamicSharedMemorySize, HG_SMEM);
    cudaFuncSetAttribute(attn_mma_kernel,
                         cudaFuncAttributeMaxDynamicSharedMemorySize, AT_SMEM);

    const int n4x = Mn * Hn / 4;
    dim3 tb(32, 8);

    // Launch order chosen so the Q-projection GEMM is the 5th launch
    // (ncu capture slot). All dependencies preserved.
    ropetab_kernel<<<Sn * 64 / 256, 256>>>();                               // 1
    split_kernel<<<n4x / 256, 256>>>(hidden, pXh, pXl, n4x);                // 2
    tsplit_kernel<<<dim3(4096 / 32, 4096 / 32), tb>>>(Wq, pQTh, pQTl, Hn, 4096); // 3
    tsplit_kernel<<<dim3(1024 / 32, 4096 / 32), tb>>>(Wk, pKTh, pKTl, Hn, 1024); // 4
    hgemm_kernel<1><<<dim3(4096 / 128, Mn / 128), 256, HG_SMEM>>>(          // 5 <- profiled
        pXh, pXl, pQTh, pQTl, nullptr, pQh, pQl, 4096, Hn);
    tsplit_kernel<<<dim3(1024 / 32, 4096 / 32), tb>>>(Wv, pVTh, pVTl, Hn, 1024); // 6
    hgemm_kernel<2><<<dim3(1024 / 128, Mn / 128), 256, HG_SMEM>>>(          // 7
        pXh, pXl, pKTh, pKTl, nullptr, pKh, pKl, 1024, Hn);
    hgemm_kernel<3><<<dim3(1024 / 128, Mn / 128), 256, HG_SMEM>>>(          // 8
        pXh, pXl, pVTh, pVTl, nullptr, pVh, pVl, 1024, Hn);
    dim3 ga(Sn / 128, NHn, Bn);
    attn_mma_kernel<<<ga, 256, AT_SMEM>>>();                                // 9
    tsplit_kernel<<<dim3(4096 / 32, 4096 / 32), tb>>>(Wo, pOTh, pOTl, 4096, Hn); // 10
    hgemm_kernel<0><<<dim3(4096 / 128, Mn / 128), 256, HG_SMEM>>>(          // 11
        pXh, pXl, pOTh, pOTl, out, nullptr, nullptr, 4096, Hn);
}